// round 2
// baseline (speedup 1.0000x reference)
#include <cuda_runtime.h>
#include <math.h>

#define BATCH 32
#define SEQ   1024
#define CIN   384
#define HD    64
#define NROWS (BATCH*SEQ)

// Scratch for projected q/k/v (fp32): 3 x 8 MB. (__device__ globals: allowed.)
__device__ float g_q[NROWS*HD];
__device__ float g_k[NROWS*HD];
__device__ float g_v[NROWS*HD];

// Swizzled column for the K tile: XOR bits [2:5) of c with (r>>2)&7.
// Keeps row-major stores conflict-free and makes column-of-rows reads 2-way max.
__device__ __forceinline__ int ksw(int r, int c) {
    return (c ^ (((r >> 2) & 7) << 2));
}

// ---------------------------------------------------------------------------
// QKV projection: out[row, h] = sum_c x[row, c] * W[c, h]
// Grid: (NROWS/64, 3) ; block 256 threads ; 64x64 output tile, K-chunks of 32.
// ---------------------------------------------------------------------------
__global__ __launch_bounds__(256) void qkv_proj(
    const float* __restrict__ x,
    const float* __restrict__ Wk,
    const float* __restrict__ Wq,
    const float* __restrict__ Wv)
{
    __shared__ float xs[64][33];   // [row][k] padded
    __shared__ float ws[32][65];   // [k][h]  padded

    const float* W;
    float* outp;
    if (blockIdx.y == 0)      { W = Wq; outp = g_q; }
    else if (blockIdx.y == 1) { W = Wk; outp = g_k; }
    else                      { W = Wv; outp = g_v; }

    const int tid = threadIdx.x;
    const int tx  = tid & 15;
    const int ty  = tid >> 4;
    const int r0  = ty * 4;
    const int c0  = tx * 4;
    const int rowbase = blockIdx.x * 64;

    float acc[4][4] = {};

    for (int k0 = 0; k0 < CIN; k0 += 32) {
        for (int i = tid; i < 64 * 32; i += 256) {
            int r = i >> 5, c = i & 31;
            xs[r][c] = x[(rowbase + r) * CIN + k0 + c];
        }
        for (int i = tid; i < 32 * 64; i += 256) {
            int r = i >> 6, c = i & 63;
            ws[r][c] = W[(k0 + r) * HD + c];
        }
        __syncthreads();

        #pragma unroll 8
        for (int kk = 0; kk < 32; kk++) {
            float a[4], bb[4];
            #pragma unroll
            for (int i = 0; i < 4; i++) a[i]  = xs[r0 + i][kk];
            #pragma unroll
            for (int j = 0; j < 4; j++) bb[j] = ws[kk][c0 + j];
            #pragma unroll
            for (int i = 0; i < 4; i++)
                #pragma unroll
                for (int j = 0; j < 4; j++)
                    acc[i][j] += a[i] * bb[j];
        }
        __syncthreads();
    }

    float4* o4 = (float4*)outp;
    #pragma unroll
    for (int i = 0; i < 4; i++) {
        o4[(rowbase + r0 + i) * (HD / 4) + tx] =
            make_float4(acc[i][0], acc[i][1], acc[i][2], acc[i][3]);
    }
}

// ---------------------------------------------------------------------------
// Flash-style causal attention.
// Grid: (SEQ/64, BATCH) ; block 256 threads.
// Each block: one batch b, 64 query rows. Streams 64-key tiles with online
// softmax. S and O in registers (4x4/thread); Q/K/V/P in static smem = 48 KB.
//   Qs[64*64] + Ks[64*64] (swizzled, aliased by Ps) + Vs[64*64] = 12288 floats.
// ---------------------------------------------------------------------------
__global__ __launch_bounds__(256) void attn_kernel(float* __restrict__ out)
{
    __shared__ float Qs[64 * 64];
    __shared__ float Ks[64 * 64];  // swizzled K^T tile; aliased by Ps (plain layout)
    __shared__ float Vs[64 * 64];
    float* Ps = Ks;

    const int tid = threadIdx.x;
    const int tx  = tid & 15;
    const int ty  = tid >> 4;
    const int r0  = ty * 4;          // query rows r0..r0+3
    const int c0  = tx * 4;          // key cols / H cols c0..c0+3

    const int b  = blockIdx.y;
    const int qt = blockIdx.x;
    const int qbase = qt * 64;

    const float* qptr = g_q + (size_t)(b * SEQ + qbase) * HD;
    for (int i = tid; i < 4096; i += 256) Qs[i] = qptr[i];

    float m[4], l[4], acc[4][4];
    #pragma unroll
    for (int i = 0; i < 4; i++) {
        m[i] = -1e30f;
        l[i] = 0.0f;
        #pragma unroll
        for (int j = 0; j < 4; j++) acc[i][j] = 0.0f;
    }

    for (int kt = 0; kt <= qt; kt++) {
        const float* kptr = g_k + (size_t)(b * SEQ + kt * 64) * HD;
        const float* vptr = g_v + (size_t)(b * SEQ + kt * 64) * HD;

        __syncthreads();  // previous iteration done reading Ps/Vs
        for (int i = tid; i < 4096; i += 256) {
            int r = i >> 6, c = i & 63;
            Ks[r * 64 + ksw(r, c)] = kptr[i];
            Vs[i]                  = vptr[i];
        }
        __syncthreads();  // tiles (and Qs on first iter) visible

        // S = Q @ K^T  (4x4 per thread)
        float s[4][4] = {};
        #pragma unroll 8
        for (int h = 0; h < HD; h++) {
            float a[4], bb[4];
            #pragma unroll
            for (int i = 0; i < 4; i++) a[i]  = Qs[(r0 + i) * 64 + h];
            #pragma unroll
            for (int j = 0; j < 4; j++) bb[j] = Ks[(c0 + j) * 64 + ksw(c0 + j, h)];
            #pragma unroll
            for (int i = 0; i < 4; i++)
                #pragma unroll
                for (int j = 0; j < 4; j++)
                    s[i][j] += a[i] * bb[j];
        }

        const float sc = 0.125f;  // H^-0.5
        if (kt == qt) {
            #pragma unroll
            for (int i = 0; i < 4; i++)
                #pragma unroll
                for (int j = 0; j < 4; j++)
                    s[i][j] = ((r0 + i) >= (c0 + j)) ? s[i][j] * sc : -1e30f;
        } else {
            #pragma unroll
            for (int i = 0; i < 4; i++)
                #pragma unroll
                for (int j = 0; j < 4; j++)
                    s[i][j] *= sc;
        }

        // Online softmax per row (16 threads share a row -> shfl reduce)
        #pragma unroll
        for (int i = 0; i < 4; i++) {
            float rmax = fmaxf(fmaxf(s[i][0], s[i][1]), fmaxf(s[i][2], s[i][3]));
            #pragma unroll
            for (int off = 8; off > 0; off >>= 1)
                rmax = fmaxf(rmax, __shfl_xor_sync(0xffffffffu, rmax, off));
            float mn    = fmaxf(m[i], rmax);
            float alpha = __expf(m[i] - mn);
            m[i] = mn;

            float rsum = 0.0f;
            #pragma unroll
            for (int j = 0; j < 4; j++) {
                s[i][j] = __expf(s[i][j] - mn);
                rsum   += s[i][j];
            }
            #pragma unroll
            for (int off = 8; off > 0; off >>= 1)
                rsum += __shfl_xor_sync(0xffffffffu, rsum, off);

            l[i] = l[i] * alpha + rsum;
            #pragma unroll
            for (int j = 0; j < 4; j++) acc[i][j] *= alpha;
        }

        __syncthreads();  // everyone done reading Ks before Ps overwrites it
        #pragma unroll
        for (int i = 0; i < 4; i++)
            ((float4*)Ps)[(r0 + i) * 16 + tx] =
                make_float4(s[i][0], s[i][1], s[i][2], s[i][3]);
        __syncthreads();

        // O += P @ V   (V read as float4, conflict-free; P broadcast)
        #pragma unroll 8
        for (int c = 0; c < 64; c++) {
            float4 bv = ((float4*)Vs)[c * 16 + tx];
            #pragma unroll
            for (int i = 0; i < 4; i++) {
                float a = Ps[(r0 + i) * 64 + c];
                acc[i][0] += a * bv.x;
                acc[i][1] += a * bv.y;
                acc[i][2] += a * bv.z;
                acc[i][3] += a * bv.w;
            }
        }
    }

    // Epilogue: normalize and store [B, T, H]
    float4* o4 = (float4*)out;
    #pragma unroll
    for (int i = 0; i < 4; i++) {
        float inv = 1.0f / l[i];
        int row = b * SEQ + qbase + r0 + i;
        o4[row * (HD / 4) + tx] =
            make_float4(acc[i][0] * inv, acc[i][1] * inv,
                        acc[i][2] * inv, acc[i][3] * inv);
    }
}

// ---------------------------------------------------------------------------
// Launch — kernel launches only; nothing else touches the runtime.
// ---------------------------------------------------------------------------
extern "C" void kernel_launch(void* const* d_in, const int* in_sizes, int n_in,
                              void* d_out, int out_size)
{
    // metadata order: x, Wk, Wq, Wv
    const float* x  = (const float*)d_in[0];
    const float* Wk = (const float*)d_in[1];
    const float* Wq = (const float*)d_in[2];
    const float* Wv = (const float*)d_in[3];
    float* out = (float*)d_out;

    dim3 gp(NROWS / 64, 3);
    qkv_proj<<<gp, 256>>>(x, Wk, Wq, Wv);

    dim3 ga(SEQ / 64, BATCH);
    attn_kernel<<<ga, 256>>>(out);
}

// round 5
// speedup vs baseline: 4.0929x; 4.0929x over previous
#include <cuda_runtime.h>
#include <cuda_fp16.h>
#include <cstdint>

#define BATCH 32
#define SEQ   1024
#define CIN   384
#define HD    64
#define NROWS (BATCH*SEQ)

// fp16 q/k/v staging (device globals: allocation-guard safe)
__device__ __half g_qh[NROWS*HD];
__device__ __half g_kh[NROWS*HD];
__device__ __half g_vh[NROWS*HD];

// SW128 swizzle on byte offsets within a 128B-row tile
#define SW128(off) ((uint32_t)(off) ^ ((((uint32_t)(off)) >> 3) & 0x70u))

__device__ __forceinline__ uint32_t smem_u32(const void* p) {
    uint32_t a;
    asm("{ .reg .u64 t; cvta.to.shared.u64 t, %1; cvt.u32.u64 %0, t; }" : "=r"(a) : "l"(p));
    return a;
}
__device__ __forceinline__ void ldsm_x4(uint32_t addr, uint32_t* r) {
    asm volatile("ldmatrix.sync.aligned.m8n8.x4.shared.b16 {%0,%1,%2,%3}, [%4];"
        : "=r"(r[0]), "=r"(r[1]), "=r"(r[2]), "=r"(r[3]) : "r"(addr));
}
__device__ __forceinline__ void ldsm_x4_t(uint32_t addr, uint32_t* r) {
    asm volatile("ldmatrix.sync.aligned.m8n8.x4.trans.shared.b16 {%0,%1,%2,%3}, [%4];"
        : "=r"(r[0]), "=r"(r[1]), "=r"(r[2]), "=r"(r[3]) : "r"(addr));
}
// D = A(16x16 f16) * B(16x8 f16) + D, f32 accumulate
__device__ __forceinline__ void mma16816(float* d, const uint32_t* a, uint32_t b0, uint32_t b1) {
    asm volatile(
        "mma.sync.aligned.m16n8k16.row.col.f32.f16.f16.f32 "
        "{%0,%1,%2,%3}, {%4,%5,%6,%7}, {%8,%9}, {%0,%1,%2,%3};"
        : "+f"(d[0]), "+f"(d[1]), "+f"(d[2]), "+f"(d[3])
        : "r"(a[0]), "r"(a[1]), "r"(a[2]), "r"(a[3]), "r"(b0), "r"(b1));
}
__device__ __forceinline__ uint32_t pack_h2(float a, float b) {
    __half2 h = __floats2half2_rn(a, b);
    return *(uint32_t*)&h;
}

// ---------------------------------------------------------------------------
// Projection: out_s[128 x 64] = x_tile[128 x 384] @ W_s  (fp16 HMMA, fp32 acc)
// grid (256, 3), 256 threads = 8 warps (4 m x 2 n), warp tile 32x32.
// fp32->fp16 conversion fused into the smem loads; 0.125 folded into Wq.
// ---------------------------------------------------------------------------
__global__ __launch_bounds__(256) void proj_kernel(
    const float* __restrict__ x,
    const float* __restrict__ Wk,
    const float* __restrict__ Wq,
    const float* __restrict__ Wv)
{
    __shared__ __align__(128) __half As[128 * 64];  // 16KB, 128B rows, SW128
    __shared__ __align__(128) __half Bs[64 * 64];   // 8KB

    const int tid = threadIdx.x, lane = tid & 31, w = tid >> 5;
    const int wm = w & 3, wn = w >> 2;
    const int s = blockIdx.y;
    const float* W = (s == 0) ? Wq : (s == 1) ? Wk : Wv;
    __half* dst    = (s == 0) ? g_qh : (s == 1) ? g_kh : g_vh;
    const float wscale = (s == 0) ? 0.125f : 1.0f;
    const int m0 = blockIdx.x * 128;

    const uint32_t aAs = smem_u32(As), aBs = smem_u32(Bs);
    float acc[2][4][4] = {};

    for (int kc = 0; kc < 6; kc++) {
        __syncthreads();
        // A: x[m0..+127][kc*64..+63] -> fp16 smem
        #pragma unroll
        for (int i = tid; i < 4096; i += 256) {
            int r = i >> 5, c2 = i & 31;
            float2 v = *(const float2*)(x + (size_t)(m0 + r) * CIN + kc * 64 + 2 * c2);
            *(__half2*)((char*)As + SW128(r * 128 + c2 * 4)) = __floats2half2_rn(v.x, v.y);
        }
        // B: W[kc*64..+63][0..63] -> fp16 smem (scaled)
        #pragma unroll
        for (int i = tid; i < 2048; i += 256) {
            int r = i >> 5, c2 = i & 31;
            float2 v = *(const float2*)(W + (size_t)(kc * 64 + r) * HD + 2 * c2);
            *(__half2*)((char*)Bs + SW128(r * 128 + c2 * 4)) =
                __floats2half2_rn(v.x * wscale, v.y * wscale);
        }
        __syncthreads();

        #pragma unroll
        for (int ks = 0; ks < 4; ks++) {
            uint32_t a[2][4];
            #pragma unroll
            for (int mf = 0; mf < 2; mf++) {
                int row = 32 * wm + 16 * mf + (lane & 15);
                ldsm_x4(aAs + SW128(row * 128 + 32 * ks + 16 * (lane >> 4)), a[mf]);
            }
            #pragma unroll
            for (int p = 0; p < 2; p++) {
                uint32_t b[4];
                int krow = 16 * ks + (lane & 15);
                int ncol = 32 * wn + 8 * (2 * p + (lane >> 4));
                ldsm_x4_t(aBs + SW128(krow * 128 + ncol * 2), b);
                #pragma unroll
                for (int mf = 0; mf < 2; mf++) {
                    mma16816(acc[mf][2 * p],     a[mf], b[0], b[1]);
                    mma16816(acc[mf][2 * p + 1], a[mf], b[2], b[3]);
                }
            }
        }
    }

    // epilogue: fp32 acc -> fp16 half2 stores
    #pragma unroll
    for (int mf = 0; mf < 2; mf++) {
        int row = m0 + 32 * wm + 16 * mf + (lane >> 2);
        #pragma unroll
        for (int nf = 0; nf < 4; nf++) {
            int c2 = 16 * wn + 4 * nf + (lane & 3);
            ((__half2*)dst)[(size_t)row * 32 + c2] =
                __floats2half2_rn(acc[mf][nf][0], acc[mf][nf][1]);
            ((__half2*)dst)[(size_t)(row + 8) * 32 + c2] =
                __floats2half2_rn(acc[mf][nf][2], acc[mf][nf][3]);
        }
    }
}

// ---------------------------------------------------------------------------
// Flash attention, fp16 HMMA, register-resident. Br=Bc=64, 128 threads,
// 4 warps x 16 query rows. grid (16, 32).
// ---------------------------------------------------------------------------
__global__ __launch_bounds__(128) void attn_kernel(float* __restrict__ out)
{
    __shared__ __align__(128) __half Qs[64 * 64];
    __shared__ __align__(128) __half Ks[64 * 64];
    __shared__ __align__(128) __half Vs[64 * 64];

    const int tid = threadIdx.x, lane = tid & 31, w = tid >> 5;
    const int b = blockIdx.y, qt = blockIdx.x;
    const uint32_t aQs = smem_u32(Qs), aKs = smem_u32(Ks), aVs = smem_u32(Vs);

    // Load Q tile (fp16, SW128)
    const uint4* qg = (const uint4*)(g_qh + (size_t)(b * SEQ + qt * 64) * HD);
    #pragma unroll
    for (int i = tid; i < 512; i += 128) {
        int r = i >> 3, cg = i & 7;
        *(uint4*)((char*)Qs + SW128(r * 128 + cg * 16)) = qg[i];
    }
    __syncthreads();

    // Preload Q fragments (warp rows 16w..16w+15, all of HD)
    uint32_t qf[4][4];
    #pragma unroll
    for (int ks = 0; ks < 4; ks++) {
        int row = 16 * w + (lane & 15);
        ldsm_x4(aQs + SW128(row * 128 + 32 * ks + 16 * (lane >> 4)), qf[ks]);
    }

    float m[2] = {-1e30f, -1e30f}, l[2] = {0.0f, 0.0f};
    float o[8][4] = {};

    for (int kt = 0; kt <= qt; kt++) {
        __syncthreads();   // previous iteration's ldmatrix reads done
        const uint4* kg = (const uint4*)(g_kh + (size_t)(b * SEQ + kt * 64) * HD);
        const uint4* vg = (const uint4*)(g_vh + (size_t)(b * SEQ + kt * 64) * HD);
        #pragma unroll
        for (int i = tid; i < 512; i += 128) {
            int r = i >> 3, cg = i & 7;
            uint32_t sw = SW128(r * 128 + cg * 16);
            *(uint4*)((char*)Ks + sw) = kg[i];
            *(uint4*)((char*)Vs + sw) = vg[i];
        }
        __syncthreads();

        // S = Q @ K^T  (B-frags from K row-major via non-trans ldmatrix)
        float sacc[8][4] = {};
        #pragma unroll
        for (int ks = 0; ks < 4; ks++) {
            #pragma unroll
            for (int p = 0; p < 4; p++) {
                uint32_t bf[4];
                int key = 16 * p + 8 * (lane >> 4) + (lane & 7);
                uint32_t off = key * 128 + 32 * ks + 16 * ((lane >> 3) & 1);
                ldsm_x4(aKs + SW128(off), bf);
                mma16816(sacc[2 * p],     qf[ks], bf[0], bf[1]);
                mma16816(sacc[2 * p + 1], qf[ks], bf[2], bf[3]);
            }
        }

        // Causal mask on the diagonal tile
        const int rA = 16 * w + (lane >> 2);   // local row (rows rA and rA+8)
        if (kt == qt) {
            #pragma unroll
            for (int nf = 0; nf < 8; nf++) {
                int c = 8 * nf + 2 * (lane & 3);
                if (c     > rA)     sacc[nf][0] = -1e30f;
                if (c + 1 > rA)     sacc[nf][1] = -1e30f;
                if (c     > rA + 8) sacc[nf][2] = -1e30f;
                if (c + 1 > rA + 8) sacc[nf][3] = -1e30f;
            }
        }

        // Online softmax (quad = 4 lanes share a row)
        float mt0 = -1e30f, mt1 = -1e30f;
        #pragma unroll
        for (int nf = 0; nf < 8; nf++) {
            mt0 = fmaxf(mt0, fmaxf(sacc[nf][0], sacc[nf][1]));
            mt1 = fmaxf(mt1, fmaxf(sacc[nf][2], sacc[nf][3]));
        }
        mt0 = fmaxf(mt0, __shfl_xor_sync(0xffffffffu, mt0, 1));
        mt0 = fmaxf(mt0, __shfl_xor_sync(0xffffffffu, mt0, 2));
        mt1 = fmaxf(mt1, __shfl_xor_sync(0xffffffffu, mt1, 1));
        mt1 = fmaxf(mt1, __shfl_xor_sync(0xffffffffu, mt1, 2));

        float mn0 = fmaxf(m[0], mt0), mn1 = fmaxf(m[1], mt1);
        float a0 = __expf(m[0] - mn0), a1 = __expf(m[1] - mn1);
        m[0] = mn0; m[1] = mn1;

        float la0 = 0.0f, la1 = 0.0f;
        uint32_t ph[8][2];
        #pragma unroll
        for (int nf = 0; nf < 8; nf++) {
            float e0 = __expf(sacc[nf][0] - mn0);
            float e1 = __expf(sacc[nf][1] - mn0);
            float e2 = __expf(sacc[nf][2] - mn1);
            float e3 = __expf(sacc[nf][3] - mn1);
            la0 += e0 + e1; la1 += e2 + e3;
            ph[nf][0] = pack_h2(e0, e1);
            ph[nf][1] = pack_h2(e2, e3);
        }
        la0 += __shfl_xor_sync(0xffffffffu, la0, 1);
        la0 += __shfl_xor_sync(0xffffffffu, la0, 2);
        la1 += __shfl_xor_sync(0xffffffffu, la1, 1);
        la1 += __shfl_xor_sync(0xffffffffu, la1, 2);
        l[0] = l[0] * a0 + la0;
        l[1] = l[1] * a1 + la1;

        #pragma unroll
        for (int nf = 0; nf < 8; nf++) {
            o[nf][0] *= a0; o[nf][1] *= a0;
            o[nf][2] *= a1; o[nf][3] *= a1;
        }

        // O += P @ V  (A-frags = reshaped P; B-frags from V via trans ldmatrix)
        #pragma unroll
        for (int ks = 0; ks < 4; ks++) {
            uint32_t pa[4] = {ph[2 * ks][0], ph[2 * ks][1],
                              ph[2 * ks + 1][0], ph[2 * ks + 1][1]};
            #pragma unroll
            for (int p = 0; p < 4; p++) {
                uint32_t vf[4];
                int krow = 16 * ks + (lane & 15);
                int n0   = 8 * (2 * p + (lane >> 4));
                ldsm_x4_t(aVs + SW128(krow * 128 + n0 * 2), vf);
                mma16816(o[2 * p],     pa, vf[0], vf[1]);
                mma16816(o[2 * p + 1], pa, vf[2], vf[3]);
            }
        }
    }

    // Epilogue: normalize and store fp32
    float inv0 = 1.0f / l[0], inv1 = 1.0f / l[1];
    int rowg = b * SEQ + qt * 64 + 16 * w + (lane >> 2);
    #pragma unroll
    for (int nf = 0; nf < 8; nf++) {
        int c = 8 * nf + 2 * (lane & 3);
        *(float2*)(out + (size_t)rowg * HD + c) =
            make_float2(o[nf][0] * inv0, o[nf][1] * inv0);
        *(float2*)(out + (size_t)(rowg + 8) * HD + c) =
            make_float2(o[nf][2] * inv1, o[nf][3] * inv1);
    }
}

// ---------------------------------------------------------------------------
// Launch
// ---------------------------------------------------------------------------
extern "C" void kernel_launch(void* const* d_in, const int* in_sizes, int n_in,
                              void* d_out, int out_size)
{
    // metadata order: x, Wk, Wq, Wv
    const float* x  = (const float*)d_in[0];
    const float* Wk = (const float*)d_in[1];
    const float* Wq = (const float*)d_in[2];
    const float* Wv = (const float*)d_in[3];
    float* out = (float*)d_out;

    dim3 gp(NROWS / 128, 3);
    proj_kernel<<<gp, 256>>>(x, Wk, Wq, Wv);

    dim3 ga(SEQ / 64, BATCH);
    attn_kernel<<<ga, 128>>>(out);
}

// round 7
// speedup vs baseline: 5.9656x; 1.4575x over previous
#include <cuda_runtime.h>
#include <cuda_fp16.h>
#include <cstdint>

#define BATCH 32
#define SEQ   1024
#define CIN   384
#define HD    64
#define NROWS (BATCH*SEQ)

// q scaled by H^-0.5 * log2(e): softmax done in exp2 domain
#define QSCALE (0.125f * 1.44269504088896f)

// fp16 q/k/v staging (device globals: allocation-guard safe)
__device__ __half g_qh[NROWS*HD];
__device__ __half g_kh[NROWS*HD];
__device__ __half g_vh[NROWS*HD];

// SW128 swizzle on byte offsets within a 128B-row tile
#define SW128(off) ((uint32_t)(off) ^ ((((uint32_t)(off)) >> 3) & 0x70u))

__device__ __forceinline__ uint32_t smem_u32(const void* p) {
    uint32_t a;
    asm("{ .reg .u64 t; cvta.to.shared.u64 t, %1; cvt.u32.u64 %0, t; }" : "=r"(a) : "l"(p));
    return a;
}
__device__ __forceinline__ void ldsm_x4(uint32_t addr, uint32_t* r) {
    asm volatile("ldmatrix.sync.aligned.m8n8.x4.shared.b16 {%0,%1,%2,%3}, [%4];"
        : "=r"(r[0]), "=r"(r[1]), "=r"(r[2]), "=r"(r[3]) : "r"(addr));
}
__device__ __forceinline__ void ldsm_x4_t(uint32_t addr, uint32_t* r) {
    asm volatile("ldmatrix.sync.aligned.m8n8.x4.trans.shared.b16 {%0,%1,%2,%3}, [%4];"
        : "=r"(r[0]), "=r"(r[1]), "=r"(r[2]), "=r"(r[3]) : "r"(addr));
}
__device__ __forceinline__ void mma16816(float* d, const uint32_t* a, uint32_t b0, uint32_t b1) {
    asm volatile(
        "mma.sync.aligned.m16n8k16.row.col.f32.f16.f16.f32 "
        "{%0,%1,%2,%3}, {%4,%5,%6,%7}, {%8,%9}, {%0,%1,%2,%3};"
        : "+f"(d[0]), "+f"(d[1]), "+f"(d[2]), "+f"(d[3])
        : "r"(a[0]), "r"(a[1]), "r"(a[2]), "r"(a[3]), "r"(b0), "r"(b1));
}
__device__ __forceinline__ uint32_t pack_h2(float a, float b) {
    __half2 h = __floats2half2_rn(a, b);
    return *(uint32_t*)&h;
}
#define CP_ASYNC16(dst, src) \
    asm volatile("cp.async.cg.shared.global [%0], [%1], 16;" :: "r"(dst), "l"(src) : "memory")
#define CP_COMMIT() asm volatile("cp.async.commit_group;" ::: "memory")
#define CP_WAIT0()  asm volatile("cp.async.wait_group 0;" ::: "memory")

// ---------------------------------------------------------------------------
// Fused QKV projection: [128 x 192] = x_tile[128 x 384] @ [Wq*s | Wk | Wv]
// grid 256 blocks, 384 threads = 12 warps (4 m x 3 n). Warp tile 32m x 64n:
// each warp column (wn) owns exactly one output panel (q / k / v).
// x read ONCE (fp32->fp16 fused into smem load).
// ---------------------------------------------------------------------------
__global__ __launch_bounds__(384) void proj_kernel(
    const float* __restrict__ x,
    const float* __restrict__ Wk,
    const float* __restrict__ Wq,
    const float* __restrict__ Wv)
{
    __shared__ __align__(128) __half As[128 * 64];      // 16KB
    __shared__ __align__(128) __half Bs[3 * 64 * 64];   // 24KB: 3 panels of 8KB

    const int tid = threadIdx.x, lane = tid & 31, w = tid >> 5;
    const int wm = w & 3, wn = w >> 2;        // wn: 0=q, 1=k, 2=v
    const int m0 = blockIdx.x * 128;
    const uint32_t aAs = smem_u32(As), aBs = smem_u32(Bs) + wn * 8192;

    float acc[2][8][4] = {};

    for (int kc = 0; kc < 6; kc++) {
        __syncthreads();
        // A: x[m0..+127][kc*64..+63] -> fp16 smem
        #pragma unroll
        for (int i = tid; i < 4096; i += 384) {
            int r = i >> 5, c2 = i & 31;
            float2 v = *(const float2*)(x + (size_t)(m0 + r) * CIN + kc * 64 + 2 * c2);
            *(__half2*)((char*)As + SW128(r * 128 + c2 * 4)) = __floats2half2_rn(v.x, v.y);
        }
        // B panels: Wq (scaled), Wk, Wv
        #pragma unroll
        for (int i = tid; i < 6144; i += 384) {
            int p = i >> 11, rem = i & 2047;
            int r = rem >> 5, c2 = rem & 31;
            const float* W = (p == 0) ? Wq : (p == 1) ? Wk : Wv;
            float sc = (p == 0) ? QSCALE : 1.0f;
            float2 v = *(const float2*)(W + (size_t)(kc * 64 + r) * HD + 2 * c2);
            *(__half2*)((char*)Bs + p * 8192 + SW128(r * 128 + c2 * 4)) =
                __floats2half2_rn(v.x * sc, v.y * sc);
        }
        __syncthreads();

        #pragma unroll
        for (int ks = 0; ks < 4; ks++) {
            uint32_t a[2][4];
            #pragma unroll
            for (int mf = 0; mf < 2; mf++) {
                int row = 32 * wm + 16 * mf + (lane & 15);
                ldsm_x4(aAs + SW128(row * 128 + 32 * ks + 16 * (lane >> 4)), a[mf]);
            }
            #pragma unroll
            for (int p = 0; p < 4; p++) {
                uint32_t bfr[4];
                int krow = 16 * ks + (lane & 15);
                int ncol = 8 * (2 * p + (lane >> 4));
                ldsm_x4_t(aBs + SW128(krow * 128 + ncol * 2), bfr);
                #pragma unroll
                for (int mf = 0; mf < 2; mf++) {
                    mma16816(acc[mf][2 * p],     a[mf], bfr[0], bfr[1]);
                    mma16816(acc[mf][2 * p + 1], a[mf], bfr[2], bfr[3]);
                }
            }
        }
    }

    __half* dst = (wn == 0) ? g_qh : (wn == 1) ? g_kh : g_vh;
    #pragma unroll
    for (int mf = 0; mf < 2; mf++) {
        int row = m0 + 32 * wm + 16 * mf + (lane >> 2);
        #pragma unroll
        for (int nf = 0; nf < 8; nf++) {
            int c2 = 4 * nf + (lane & 3);
            ((__half2*)dst)[(size_t)row * 32 + c2] =
                __floats2half2_rn(acc[mf][nf][0], acc[mf][nf][1]);
            ((__half2*)dst)[(size_t)(row + 8) * 32 + c2] =
                __floats2half2_rn(acc[mf][nf][2], acc[mf][nf][3]);
        }
    }
}

// ---------------------------------------------------------------------------
// Flash attention, fp16 HMMA, register-resident, cp.async double-buffered K/V.
// Br=Bc=64, 128 threads (4 warps x 16 query rows). grid (16, 32).
// ---------------------------------------------------------------------------
__global__ __launch_bounds__(128) void attn_kernel(float* __restrict__ out)
{
    __shared__ __align__(128) __half Qs[64 * 64];
    __shared__ __align__(128) __half Ks[2][64 * 64];
    __shared__ __align__(128) __half Vs[2][64 * 64];

    const int tid = threadIdx.x, lane = tid & 31, w = tid >> 5;
    const int b = blockIdx.y, qt = blockIdx.x;
    const uint32_t aQs = smem_u32(Qs);
    const uint32_t aK0 = smem_u32(Ks), aV0 = smem_u32(Vs);

    const __half* kbase = g_kh + (size_t)b * SEQ * HD;
    const __half* vbase = g_vh + (size_t)b * SEQ * HD;

    // Load Q tile (regular stores)
    const uint4* qg = (const uint4*)(g_qh + (size_t)(b * SEQ + qt * 64) * HD);
    #pragma unroll
    for (int i = tid; i < 512; i += 128) {
        int r = i >> 3, cg = i & 7;
        *(uint4*)((char*)Qs + SW128(r * 128 + cg * 16)) = qg[i];
    }

    // Prefetch K/V tile 0 into stage 0
    {
        const uint4* kg = (const uint4*)kbase;
        const uint4* vg = (const uint4*)vbase;
        #pragma unroll
        for (int i = tid; i < 512; i += 128) {
            int r = i >> 3, cg = i & 7;
            uint32_t sw = SW128(r * 128 + cg * 16);
            CP_ASYNC16(aK0 + sw, kg + i);
            CP_ASYNC16(aV0 + sw, vg + i);
        }
        CP_COMMIT();
    }
    __syncthreads();   // Qs visible

    // Preload Q fragments
    uint32_t qf[4][4];
    #pragma unroll
    for (int ks = 0; ks < 4; ks++) {
        int row = 16 * w + (lane & 15);
        ldsm_x4(aQs + SW128(row * 128 + 32 * ks + 16 * (lane >> 4)), qf[ks]);
    }

    float m[2] = {-1e30f, -1e30f}, l[2] = {0.0f, 0.0f};
    float o[8][4] = {};
    int st = 0;

    for (int kt = 0; kt <= qt; kt++) {
        CP_WAIT0();
        __syncthreads();   // tile kt ready; all reads of stage st^1 finished

        // Prefetch kt+1 into the other stage (overlaps with compute below)
        if (kt < qt) {
            const uint4* kg = (const uint4*)(kbase + (size_t)(kt + 1) * 64 * HD);
            const uint4* vg = (const uint4*)(vbase + (size_t)(kt + 1) * 64 * HD);
            uint32_t dK = aK0 + (st ^ 1) * 8192, dV = aV0 + (st ^ 1) * 8192;
            #pragma unroll
            for (int i = tid; i < 512; i += 128) {
                int r = i >> 3, cg = i & 7;
                uint32_t sw = SW128(r * 128 + cg * 16);
                CP_ASYNC16(dK + sw, kg + i);
                CP_ASYNC16(dV + sw, vg + i);
            }
            CP_COMMIT();
        }

        const uint32_t aKs = aK0 + st * 8192, aVs = aV0 + st * 8192;

        // S = Q @ K^T
        float sacc[8][4] = {};
        #pragma unroll
        for (int ks = 0; ks < 4; ks++) {
            #pragma unroll
            for (int p = 0; p < 4; p++) {
                uint32_t bf[4];
                int key = 16 * p + 8 * (lane >> 4) + (lane & 7);
                uint32_t off = key * 128 + 32 * ks + 16 * ((lane >> 3) & 1);
                ldsm_x4(aKs + SW128(off), bf);
                mma16816(sacc[2 * p],     qf[ks], bf[0], bf[1]);
                mma16816(sacc[2 * p + 1], qf[ks], bf[2], bf[3]);
            }
        }

        // Causal mask on the diagonal tile
        const int rA = 16 * w + (lane >> 2);
        if (kt == qt) {
            #pragma unroll
            for (int nf = 0; nf < 8; nf++) {
                int c = 8 * nf + 2 * (lane & 3);
                if (c     > rA)     sacc[nf][0] = -1e30f;
                if (c + 1 > rA)     sacc[nf][1] = -1e30f;
                if (c     > rA + 8) sacc[nf][2] = -1e30f;
                if (c + 1 > rA + 8) sacc[nf][3] = -1e30f;
            }
        }

        // Online softmax in exp2 domain (quad = 4 lanes share a row)
        float mt0 = -1e30f, mt1 = -1e30f;
        #pragma unroll
        for (int nf = 0; nf < 8; nf++) {
            mt0 = fmaxf(mt0, fmaxf(sacc[nf][0], sacc[nf][1]));
            mt1 = fmaxf(mt1, fmaxf(sacc[nf][2], sacc[nf][3]));
        }
        mt0 = fmaxf(mt0, __shfl_xor_sync(0xffffffffu, mt0, 1));
        mt0 = fmaxf(mt0, __shfl_xor_sync(0xffffffffu, mt0, 2));
        mt1 = fmaxf(mt1, __shfl_xor_sync(0xffffffffu, mt1, 1));
        mt1 = fmaxf(mt1, __shfl_xor_sync(0xffffffffu, mt1, 2));

        float mn0 = fmaxf(m[0], mt0), mn1 = fmaxf(m[1], mt1);
        float a0 = exp2f(m[0] - mn0), a1 = exp2f(m[1] - mn1);
        m[0] = mn0; m[1] = mn1;

        float la0 = 0.0f, la1 = 0.0f;
        uint32_t ph[8][2];
        #pragma unroll
        for (int nf = 0; nf < 8; nf++) {
            float e0 = exp2f(sacc[nf][0] - mn0);
            float e1 = exp2f(sacc[nf][1] - mn0);
            float e2 = exp2f(sacc[nf][2] - mn1);
            float e3 = exp2f(sacc[nf][3] - mn1);
            la0 += e0 + e1; la1 += e2 + e3;
            ph[nf][0] = pack_h2(e0, e1);
            ph[nf][1] = pack_h2(e2, e3);
        }
        la0 += __shfl_xor_sync(0xffffffffu, la0, 1);
        la0 += __shfl_xor_sync(0xffffffffu, la0, 2);
        la1 += __shfl_xor_sync(0xffffffffu, la1, 1);
        la1 += __shfl_xor_sync(0xffffffffu, la1, 2);
        l[0] = l[0] * a0 + la0;
        l[1] = l[1] * a1 + la1;

        #pragma unroll
        for (int nf = 0; nf < 8; nf++) {
            o[nf][0] *= a0; o[nf][1] *= a0;
            o[nf][2] *= a1; o[nf][3] *= a1;
        }

        // O += P @ V
        #pragma unroll
        for (int ks = 0; ks < 4; ks++) {
            uint32_t pa[4] = {ph[2 * ks][0], ph[2 * ks][1],
                              ph[2 * ks + 1][0], ph[2 * ks + 1][1]};
            #pragma unroll
            for (int p = 0; p < 4; p++) {
                uint32_t vf[4];
                int krow = 16 * ks + (lane & 15);
                int n0   = 8 * (2 * p + (lane >> 4));
                ldsm_x4_t(aVs + SW128(krow * 128 + n0 * 2), vf);
                mma16816(o[2 * p],     pa, vf[0], vf[1]);
                mma16816(o[2 * p + 1], pa, vf[2], vf[3]);
            }
        }
        st ^= 1;
    }

    // Epilogue: normalize and store fp32
    float inv0 = 1.0f / l[0], inv1 = 1.0f / l[1];
    int rowg = b * SEQ + qt * 64 + 16 * w + (lane >> 2);
    #pragma unroll
    for (int nf = 0; nf < 8; nf++) {
        int c = 8 * nf + 2 * (lane & 3);
        *(float2*)(out + (size_t)rowg * HD + c) =
            make_float2(o[nf][0] * inv0, o[nf][1] * inv0);
        *(float2*)(out + (size_t)(rowg + 8) * HD + c) =
            make_float2(o[nf][2] * inv1, o[nf][3] * inv1);
    }
}

// ---------------------------------------------------------------------------
// Launch
// ---------------------------------------------------------------------------
extern "C" void kernel_launch(void* const* d_in, const int* in_sizes, int n_in,
                              void* d_out, int out_size)
{
    // metadata order: x, Wk, Wq, Wv
    const float* x  = (const float*)d_in[0];
    const float* Wk = (const float*)d_in[1];
    const float* Wq = (const float*)d_in[2];
    const float* Wv = (const float*)d_in[3];
    float* out = (float*)d_out;

    proj_kernel<<<NROWS / 128, 384>>>(x, Wk, Wq, Wv);

    dim3 ga(SEQ / 64, BATCH);
    attn_kernel<<<ga, 128>>>(out);
}